// round 14
// baseline (speedup 1.0000x reference)
#include <cuda_runtime.h>
#include <cuda_bf16.h>
#include <cuda_fp16.h>

typedef unsigned int uint32;

#define EPS 1e-5f
#define TILE_F 8704    // blob: K-fp16x2 2112 | V-fp16 4224 | A-f32 2112 | pad

// ---------------- scratch (device globals; no cudaMalloc allowed) ----------------
__device__ float g_ball[768];               // folded biases
__device__ float g_qk[16 * 256 * 1024];     // [b][o][n], o<128: q, o in [128,256): k
__device__ __align__(16) uint2 g_Whs[768 * 256];        // W fp16 (big,residual) pairs [o][kpair]
__device__ __align__(16) uint32 g_Wh[768 * 256];        // W fp16 pairs (V path)
__device__ __align__(16) uint32 g_Xh[16 * 256 * 1024];  // X fp16 big pairs [b][kpair][n]
__device__ __align__(16) uint32 g_Xr[16 * 256 * 1024];  // X fp16 residual pairs
__device__ float g_B[16 * 4 * 32 * 1024];               // B[b,h][i][m] (log2e-scaled)
__device__ __align__(16) float g_tile[16 * 4 * 16 * TILE_F]; // fragment-ready tiles

// ---------------- mma / pack helpers ----------------
__device__ __forceinline__ void mma_fp16(float* c, const uint32* a, uint32 b0, uint32 b1) {
    asm volatile("mma.sync.aligned.m16n8k16.row.col.f32.f16.f16.f32 "
        "{%0,%1,%2,%3}, {%4,%5,%6,%7}, {%8,%9}, {%0,%1,%2,%3};"
        : "+f"(c[0]), "+f"(c[1]), "+f"(c[2]), "+f"(c[3])
        : "r"(a[0]), "r"(a[1]), "r"(a[2]), "r"(a[3]), "r"(b0), "r"(b1));
}
__device__ __forceinline__ uint32 pack_h2(float v0, float v1) {
    __half2 h = __floats2half2_rn(v0, v1);
    return *reinterpret_cast<uint32*>(&h);
}
__device__ __forceinline__ void split2_h(float v0, float v1, uint32& ff, uint32& rr) {
    float f0 = __half2float(__float2half_rn(v0));
    float f1 = __half2float(__float2half_rn(v1));
    ff = pack_h2(f0, f1);
    rr = pack_h2(v0 - f0, v1 - f1);
}
__device__ __forceinline__ float ex2f(float x) {
    float r; asm("ex2.approx.ftz.f32 %0, %1;" : "=f"(r) : "f"(x)); return r;
}

// ---------------- cp.async helpers ----------------
__device__ __forceinline__ void cp16(uint32 sdst, const void* gsrc) {
    asm volatile("cp.async.cg.shared.global [%0], [%1], 16;\n" :: "r"(sdst), "l"(gsrc));
}
#define CP_COMMIT() asm volatile("cp.async.commit_group;\n" ::: "memory")
#define CP_WAIT0()  asm volatile("cp.async.wait_group 0;\n" ::: "memory")
#define CP_WAIT1()  asm volatile("cp.async.wait_group 1;\n" ::: "memory")

// 128-thread blob copy (8704 floats = 2176 float4 = 17 iters)
__device__ __forceinline__ void cp_tile(float* smem_dst, const float* gsrc, int tid) {
    uint32 s = (uint32)__cvta_generic_to_shared(smem_dst);
    #pragma unroll
    for (int it = 0; it < 17; it++) {
        int i = tid + it * 128;
        cp16(s + i * 16, gsrc + i * 4);
    }
}

// ---------------- 1) fold BN; write W fp16 images ----------------
__global__ void fold_kernel(
    const float* __restrict__ Wq, const float* __restrict__ bq,
    const float* __restrict__ qg, const float* __restrict__ qb,
    const float* __restrict__ qm, const float* __restrict__ qvv,
    const float* __restrict__ Wk, const float* __restrict__ bk,
    const float* __restrict__ kg, const float* __restrict__ kb,
    const float* __restrict__ km, const float* __restrict__ kvv,
    const float* __restrict__ Wv, const float* __restrict__ bv,
    const float* __restrict__ vg, const float* __restrict__ vb,
    const float* __restrict__ vm, const float* __restrict__ vvv)
{
    int o = blockIdx.x;
    const float* src;
    float s, bias;
    if (o < 128) {
        s = qg[o] * rsqrtf(qvv[o] + EPS);
        bias = (bq[o] - qm[o]) * s + qb[o];
        src = Wq + o * 512;
    } else if (o < 256) {
        int oo = o - 128;
        s = kg[oo] * rsqrtf(kvv[oo] + EPS);
        bias = (bk[oo] - km[oo]) * s + kb[oo];
        src = Wk + oo * 512;
    } else {
        int oo = o - 256;
        s = vg[oo] * rsqrtf(vvv[oo] + EPS);
        bias = (bv[oo] - vm[oo]) * s + vb[oo];
        src = Wv + oo * 512;
    }
    int p = threadIdx.x;
    float w0 = src[2 * p] * s;
    float w1 = src[2 * p + 1] * s;
    uint32 ff, rr;
    split2_h(w0, w1, ff, rr);
    g_Whs[o * 256 + p] = make_uint2(ff, rr);
    g_Wh[o * 256 + p] = ff;
    if (p == 0) g_ball[o] = bias;
}

// ---------------- 2) X -> fp16 big + residual pair images ----------------
__global__ __launch_bounds__(256) void xsplit_kernel(const float* __restrict__ x) {
    int kp = blockIdx.x, b = blockIdx.y;
    int tid = threadIdx.x;
    const float* r0 = x + ((size_t)b * 512 + 2 * kp) * 1024;
    const float* r1 = r0 + 1024;
    uint32* df = g_Xh + ((size_t)b * 256 + kp) * 1024;
    uint32* dr = g_Xr + ((size_t)b * 256 + kp) * 1024;
    int n4 = tid * 4;
    float4 a = *(const float4*)&r0[n4];
    float4 c = *(const float4*)&r1[n4];
    uint4 fv, rv;
    split2_h(a.x, c.x, fv.x, rv.x);
    split2_h(a.y, c.y, fv.y, rv.y);
    split2_h(a.z, c.z, fv.z, rv.z);
    split2_h(a.w, c.w, fv.w, rv.w);
    *(uint4*)&df[n4] = fv;
    *(uint4*)&dr[n4] = rv;
}

// ---------------- 3) QKV projection (3-stage pipeline) ----------------
// QK (rb<2): fp16 3-term (Wf·Xf + Wr·Xf + Wf·Xr) -> g_qk
// V  (rb>=2): fp16 1-term -> V region of g_tile blob
#define PBQK_U1 9472   // sW uint2[128][20]=5120 | sXf[16][136]=2176 | sXr=2176
#define PBV_U1 4736
#define PROJ_SMEM_BYTES 113664   // 3 * 9472 * 4

__device__ __forceinline__ void cp_projqk(uint32* buf, int b, int row0, int col0, int kt, int tid) {
    uint32 s = (uint32)__cvta_generic_to_shared(buf);
    #pragma unroll
    for (int it = 0; it < 4; it++) {
        int i = tid + it * 256;
        int m = i >> 3, c = i & 7;
        cp16(s + (m * 20 + 2 * c) * 8, g_Whs + (size_t)(row0 + m) * 256 + kt * 16 + 2 * c);
    }
    #pragma unroll
    for (int it = 0; it < 2; it++) {
        int i = tid + it * 256;
        int kp = i >> 5, c = i & 31;
        cp16(s + (5120 + kp * 136 + 4 * c) * 4,
             g_Xh + ((size_t)b * 256 + kt * 16 + kp) * 1024 + col0 + 4 * c);
    }
    #pragma unroll
    for (int it = 0; it < 2; it++) {
        int i = tid + it * 256;
        int kp = i >> 5, c = i & 31;
        cp16(s + (7296 + kp * 136 + 4 * c) * 4,
             g_Xr + ((size_t)b * 256 + kt * 16 + kp) * 1024 + col0 + 4 * c);
    }
}

__device__ __forceinline__ void cp_projv(uint32* buf, int b, int row0, int col0, int kt, int tid) {
    uint32 s = (uint32)__cvta_generic_to_shared(buf);
    #pragma unroll
    for (int it = 0; it < 2; it++) {
        int i = tid + it * 256;
        int m = i >> 2, c = i & 3;
        cp16(s + (m * 20 + 4 * c) * 4, g_Wh + (size_t)(row0 + m) * 256 + kt * 16 + 4 * c);
    }
    #pragma unroll
    for (int it = 0; it < 2; it++) {
        int i = tid + it * 256;
        int kp = i >> 5, c = i & 31;
        cp16(s + (2560 + kp * 136 + 4 * c) * 4,
             g_Xh + ((size_t)b * 256 + kt * 16 + kp) * 1024 + col0 + 4 * c);
    }
}

__global__ __launch_bounds__(256) void proj_kernel() {
    extern __shared__ float ps[];
    int b = blockIdx.z, row0 = blockIdx.y * 128, col0 = blockIdx.x * 128;
    bool isV = (row0 >= 256);
    int tid = threadIdx.x, w = tid >> 5, lane = tid & 31;
    int g = lane >> 2, kk = lane & 3;
    int wm = w >> 1, wn = w & 1;

    float acc[2][8][4];
    #pragma unroll
    for (int mi = 0; mi < 2; mi++)
        #pragma unroll
        for (int nf = 0; nf < 8; nf++)
            #pragma unroll
            for (int j = 0; j < 4; j++) acc[mi][nf][j] = 0.f;

    if (!isV) {
        uint32* sbase = (uint32*)ps;
        cp_projqk(sbase, b, row0, col0, 0, tid);
        CP_COMMIT();
        cp_projqk(sbase + PBQK_U1, b, row0, col0, 1, tid);
        CP_COMMIT();
        int bufidx = 0;
        for (int kt = 0; kt < 16; kt++) {
            CP_WAIT1();
            __syncthreads();
            if (kt < 14) {
                int nb = bufidx + 2; if (nb >= 3) nb -= 3;
                cp_projqk(sbase + nb * PBQK_U1, b, row0, col0, kt + 2, tid);
                CP_COMMIT();
            }
            uint32* cur = sbase + bufidx * PBQK_U1;
            uint2* sW = (uint2*)cur;
            uint32* sXf = cur + 5120;
            uint32* sXr = cur + 7296;
            #pragma unroll
            for (int kc = 0; kc < 2; kc++) {
                uint32 Af[2][4], Ar[2][4];
                #pragma unroll
                for (int mi = 0; mi < 2; mi++) {
                    int r = wm * 32 + mi * 16 + g;
                    uint2 w0 = sW[r * 20 + kk + 8 * kc];
                    uint2 w1 = sW[(r + 8) * 20 + kk + 8 * kc];
                    uint2 w2 = sW[r * 20 + kk + 4 + 8 * kc];
                    uint2 w3 = sW[(r + 8) * 20 + kk + 4 + 8 * kc];
                    Af[mi][0] = w0.x; Af[mi][1] = w1.x; Af[mi][2] = w2.x; Af[mi][3] = w3.x;
                    Ar[mi][0] = w0.y; Ar[mi][1] = w1.y; Ar[mi][2] = w2.y; Ar[mi][3] = w3.y;
                }
                #pragma unroll
                for (int nf = 0; nf < 8; nf++) {
                    int nc = wn * 64 + 8 * nf + g;
                    uint32 xf0 = sXf[(kk + 8 * kc) * 136 + nc];
                    uint32 xf1 = sXf[(kk + 4 + 8 * kc) * 136 + nc];
                    uint32 xr0 = sXr[(kk + 8 * kc) * 136 + nc];
                    uint32 xr1 = sXr[(kk + 4 + 8 * kc) * 136 + nc];
                    #pragma unroll
                    for (int mi = 0; mi < 2; mi++) {
                        mma_fp16(acc[mi][nf], Af[mi], xf0, xf1);
                        mma_fp16(acc[mi][nf], Ar[mi], xf0, xf1);
                        mma_fp16(acc[mi][nf], Af[mi], xr0, xr1);
                    }
                }
            }
            if (++bufidx == 3) bufidx = 0;
        }
        #pragma unroll
        for (int mi = 0; mi < 2; mi++) {
            int o0 = row0 + wm * 32 + mi * 16 + g;
            int o1 = o0 + 8;
            float b0v = g_ball[o0], b1v = g_ball[o1];
            #pragma unroll
            for (int nf = 0; nf < 8; nf++) {
                int n = col0 + wn * 64 + 8 * nf + 2 * kk;
                *(float2*)&g_qk[((size_t)b * 256 + o0) * 1024 + n] =
                    make_float2(acc[mi][nf][0] + b0v, acc[mi][nf][1] + b0v);
                *(float2*)&g_qk[((size_t)b * 256 + o1) * 1024 + n] =
                    make_float2(acc[mi][nf][2] + b1v, acc[mi][nf][3] + b1v);
            }
        }
    } else {
        uint32* sbase = (uint32*)ps;
        cp_projv(sbase, b, row0, col0, 0, tid);
        CP_COMMIT();
        cp_projv(sbase + PBV_U1, b, row0, col0, 1, tid);
        CP_COMMIT();
        int bufidx = 0;
        for (int kt = 0; kt < 16; kt++) {
            CP_WAIT1();
            __syncthreads();
            if (kt < 14) {
                int nb = bufidx + 2; if (nb >= 3) nb -= 3;
                cp_projv(sbase + nb * PBV_U1, b, row0, col0, kt + 2, tid);
                CP_COMMIT();
            }
            uint32* cur = sbase + bufidx * PBV_U1;
            uint32* sW = cur;
            uint32* sX = cur + 2560;
            #pragma unroll
            for (int kc = 0; kc < 2; kc++) {
                uint32 A[2][4];
                #pragma unroll
                for (int mi = 0; mi < 2; mi++) {
                    int r = wm * 32 + mi * 16 + g;
                    A[mi][0] = sW[r * 20 + kk + 8 * kc];
                    A[mi][1] = sW[(r + 8) * 20 + kk + 8 * kc];
                    A[mi][2] = sW[r * 20 + kk + 4 + 8 * kc];
                    A[mi][3] = sW[(r + 8) * 20 + kk + 4 + 8 * kc];
                }
                #pragma unroll
                for (int nf = 0; nf < 8; nf++) {
                    int nc = wn * 64 + 8 * nf + g;
                    uint32 x0 = sX[(kk + 8 * kc) * 136 + nc];
                    uint32 x1 = sX[(kk + 4 + 8 * kc) * 136 + nc];
                    #pragma unroll
                    for (int mi = 0; mi < 2; mi++)
                        mma_fp16(acc[mi][nf], A[mi], x0, x1);
                }
            }
            if (++bufidx == 3) bufidx = 0;
        }
        CP_WAIT0();
        __syncthreads();
        float* sOut = ps;   // 128 n x 132
        #pragma unroll
        for (int mi = 0; mi < 2; mi++) {
            int o0 = row0 + wm * 32 + mi * 16 + g;
            int ol = wm * 32 + mi * 16 + g;
            float b0v = g_ball[o0], b1v = g_ball[o0 + 8];
            #pragma unroll
            for (int nf = 0; nf < 8; nf++) {
                int n = wn * 64 + 8 * nf + 2 * kk;
                sOut[n * 132 + ol] = acc[mi][nf][0] + b0v;
                sOut[(n + 1) * 132 + ol] = acc[mi][nf][1] + b0v;
                sOut[n * 132 + ol + 8] = acc[mi][nf][2] + b1v;
                sOut[(n + 1) * 132 + ol + 8] = acc[mi][nf][3] + b1v;
            }
        }
        __syncthreads();
        int h = (row0 - 256) >> 7;
        float* tb0 = g_tile + ((size_t)((b * 4 + h) * 16) + (col0 >> 6)) * TILE_F + 2112;
        #pragma unroll
        for (int it = 0; it < 16; it++) {
            int idx = tid + it * 256;     // 4096: c 0..127, dp 0..15, ntl 0..1
            int c = idx & 127, dp = (idx >> 7) & 15, ntl = idx >> 11;
            int r0 = 16 * (dp >> 2) + 2 * (dp & 3) + ntl * 64;
            uint2 val = make_uint2(
                pack_h2(sOut[r0 * 132 + c],       sOut[(r0 + 1) * 132 + c]),
                pack_h2(sOut[(r0 + 8) * 132 + c], sOut[(r0 + 9) * 132 + c]));
            ((uint2*)(tb0 + (size_t)ntl * TILE_F))[dp * 132 + c] = val;
        }
    }
}

// ---------------- 3.5) prep: K-image (fp16 big+residual planes, k-dim 32) ----------------
__global__ __launch_bounds__(256) void prep_kernel() {
    int nt = blockIdx.x, h = blockIdx.y, b = blockIdx.z;
    int tid = threadIdx.x;
    int ng = nt * 64;
    size_t kb = (size_t)16 * 256 * 1024 * 0 + (size_t)b * 256 * 1024 + (size_t)(128 + h * 32) * 1024;
    float* dst = g_tile + (size_t)((b * 4 + h) * 16 + nt) * TILE_F;

    #pragma unroll
    for (int it = 0; it < 2; it++) {
        int i = tid + it * 256;          // 512 items: 8 dp x 64 n
        int dp = i >> 6, n = i & 63;
        int kc = dp >> 2, kkp = dp & 3;
        int r0 = 16 * kc + 2 * kkp;
        float v0 = g_qk[kb + (size_t)r0 * 1024 + ng + n];
        float v1 = g_qk[kb + (size_t)(r0 + 1) * 1024 + ng + n];
        float v8 = g_qk[kb + (size_t)(r0 + 8) * 1024 + ng + n];
        float v9 = g_qk[kb + (size_t)(r0 + 9) * 1024 + ng + n];
        uint4 o;
        split2_h(v0, v1, o.x, o.z);
        split2_h(v8, v9, o.y, o.w);
        ((uint4*)dst)[dp * 66 + n] = o;
    }
}

// ---------------- 3.6) posq: A = log2e·rel_h^T·q (into blob), B = log2e·rel_w^T·q ----------------
__global__ __launch_bounds__(256) void posq_kernel(const float* __restrict__ rel_h,
                                                   const float* __restrict__ rel_w)
{
    __shared__ float sq[32 * 68];    // q[d][m-local]
    __shared__ float srh[32 * 32];   // rel_h[d][j]
    __shared__ float srw[32 * 32];   // rel_w[d][i]
    int nt = blockIdx.x, h = blockIdx.y, b = blockIdx.z;
    int tid = threadIdx.x;
    int ng = nt * 64;
    size_t qb = (size_t)b * 256 * 1024 + (size_t)(h * 32) * 1024;

    #pragma unroll
    for (int it = 0; it < 8; it++) {
        int i = tid + it * 256;      // 2048: d = i>>6, m = i&63
        sq[(i >> 6) * 68 + (i & 63)] = g_qk[qb + (size_t)(i >> 6) * 1024 + ng + (i & 63)];
    }
    #pragma unroll
    for (int it = 0; it < 4; it++) {
        int i = tid + it * 256;      // 1024
        srh[i] = rel_h[h * 1024 + i];
        srw[i] = rel_w[h * 1024 + i];
    }
    __syncthreads();

    const float LOG2E = 1.4426950408889634f;
    int m = tid & 63;
    int j0 = (tid >> 6) * 8;
    float accA[8], accB[8];
    #pragma unroll
    for (int t = 0; t < 8; t++) { accA[t] = 0.f; accB[t] = 0.f; }
    for (int d = 0; d < 32; d++) {
        float qv = sq[d * 68 + m];
        const float* rh = &srh[d * 32 + j0];
        const float* rw = &srw[d * 32 + j0];
        #pragma unroll
        for (int t = 0; t < 8; t++) {
            accA[t] += rh[t] * qv;
            accB[t] += rw[t] * qv;
        }
    }
    float* adst = g_tile + (size_t)((b * 4 + h) * 16 + nt) * TILE_F + 6336;
    float* bdst = g_B + ((size_t)(b * 4 + h) * 32) * 1024 + ng;
    #pragma unroll
    for (int t = 0; t < 8; t++) {
        adst[(j0 + t) * 66 + m] = accA[t] * LOG2E;
        bdst[(size_t)(j0 + t) * 1024 + m] = accB[t] * LOG2E;
    }
}

// ---------------- 4) flash attention: k32 fp16x3 QK + A/B adds + fp16 PV ----------------
#define ATTN_SMEM_FLOATS (2 * TILE_F + 256)   // 17664 floats = 70656 B, 3 CTAs/SM

__global__ __launch_bounds__(128, 3) void attn_kernel(const float* __restrict__ x,
                                                      float* __restrict__ out)
{
    extern __shared__ float sm[];
    int mt = blockIdx.x, h = blockIdx.y, b = blockIdx.z;
    int tid = threadIdx.x, w = tid >> 5, lane = tid & 31;
    int g = lane >> 2, kk = lane & 3;
    int mg = mt * 64;
    int rl = 16 * w + g, rh = rl + 8;
    size_t qkbase = (size_t)b * 256 * 1024;
    const float* tbase = g_tile + (size_t)((b * 4 + h) * 16) * TILE_F;
    const float* bbase = g_B + ((size_t)(b * 4 + h) * 32 + (mg >> 5)) * 1024;
    float* sB = sm + 2 * TILE_F;   // [2 buf][2 rows][64]

    cp_tile(sm, tbase, tid);
    if (tid < 32) {
        int row = tid >> 4, c4 = (tid & 15) << 2;
        cp16((uint32)__cvta_generic_to_shared(&sB[row * 64 + c4]),
             bbase + (size_t)row * 1024 + c4);
    }
    CP_COMMIT();

    // stage Q [64 m][36] (q rows only, transposed)
    float* sQ = sm + TILE_F;
    #pragma unroll
    for (int it = 0; it < 4; it++) {
        int i = tid + it * 128;   // 512 float4 units: 32 d x 16 m4
        int d = i >> 4, m4 = (i & 15) << 2;
        float4 v = *(const float4*)&g_qk[qkbase + (size_t)(h * 32 + d) * 1024 + mg + m4];
        sQ[(m4 + 0) * 36 + d] = v.x;
        sQ[(m4 + 1) * 36 + d] = v.y;
        sQ[(m4 + 2) * 36 + d] = v.z;
        sQ[(m4 + 3) * 36 + d] = v.w;
    }
    __syncthreads();

    const float LOG2E = 1.4426950408889634f;
    uint32 Qf[2][4], Qr[2][4];
    #pragma unroll
    for (int kc = 0; kc < 2; kc++) {
        int klo = 16 * kc + 2 * kk;
        int khi = klo + 8;
        split2_h(LOG2E * sQ[rl * 36 + klo], LOG2E * sQ[rl * 36 + klo + 1], Qf[kc][0], Qr[kc][0]);
        split2_h(LOG2E * sQ[rh * 36 + klo], LOG2E * sQ[rh * 36 + klo + 1], Qf[kc][1], Qr[kc][1]);
        split2_h(LOG2E * sQ[rl * 36 + khi], LOG2E * sQ[rl * 36 + khi + 1], Qf[kc][2], Qr[kc][2]);
        split2_h(LOG2E * sQ[rh * 36 + khi], LOG2E * sQ[rh * 36 + khi + 1], Qf[kc][3], Qr[kc][3]);
    }
    float m_l = -1e30f, m_h = -1e30f, l_l = 0.f, l_h = 0.f;
    float O[16][4];
    #pragma unroll
    for (int cf = 0; cf < 16; cf++)
        #pragma unroll
        for (int j = 0; j < 4; j++) O[cf][j] = 0.f;

    CP_WAIT0();
    __syncthreads();

    int jl = rl & 31, jh = rh & 31;
    int il = rl >> 5, ih2 = rh >> 5;

    for (int nt = 0; nt < 16; nt++) {
        float* buf = sm + (nt & 1) * TILE_F;
        if (nt < 15) {
            cp_tile(sm + ((nt + 1) & 1) * TILE_F, tbase + (size_t)(nt + 1) * TILE_F, tid);
            if (tid < 32) {
                int row = tid >> 4, c4 = (tid & 15) << 2;
                cp16((uint32)__cvta_generic_to_shared(
                         &sB[((nt + 1) & 1) * 128 + row * 64 + c4]),
                     bbase + (size_t)row * 1024 + (nt + 1) * 64 + c4);
            }
            CP_COMMIT();
        }
        const uint4* cK4 = (const uint4*)buf;
        const uint2* cV2 = (const uint2*)(buf + 2112);
        const float* cA = buf + 6336;
        const float* cBl = &sB[(nt & 1) * 128 + il * 64];
        const float* cBh = &sB[(nt & 1) * 128 + ih2 * 64];

        // ---- S = q·k (fp16 3-term, k-dim 32) ----
        float S[8][4];
        #pragma unroll
        for (int f = 0; f < 8; f++)
            #pragma unroll
            for (int j = 0; j < 4; j++) S[f][j] = 0.f;
        #pragma unroll
        for (int kc = 0; kc < 2; kc++) {
            const uint4* kr = cK4 + (4 * kc + kk) * 66 + g;
            #pragma unroll
            for (int f = 0; f < 8; f++) {
                uint4 kb = kr[8 * f];
                mma_fp16(S[f], Qf[kc], kb.x, kb.y);
                mma_fp16(S[f], Qr[kc], kb.x, kb.y);
                mma_fp16(S[f], Qf[kc], kb.z, kb.w);
            }
        }
        // ---- add pos contribution: A[j][c] + B[i][c] ----
        #pragma unroll
        for (int f = 0; f < 8; f++) {
            int c = 8 * f + 2 * kk;
            float2 al = *(const float2*)&cA[jl * 66 + c];
            float2 ah = *(const float2*)&cA[jh * 66 + c];
            float2 bl = *(const float2*)&cBl[c];
            float2 bh = *(const float2*)&cBh[c];
            S[f][0] += al.x + bl.x;
            S[f][1] += al.y + bl.y;
            S[f][2] += ah.x + bh.x;
            S[f][3] += ah.y + bh.y;
        }

        float mlo = -1e30f, mhi = -1e30f;
        #pragma unroll
        for (int f = 0; f < 8; f++) {
            mlo = fmaxf(mlo, fmaxf(S[f][0], S[f][1]));
            mhi = fmaxf(mhi, fmaxf(S[f][2], S[f][3]));
        }
        mlo = fmaxf(mlo, __shfl_xor_sync(0xffffffffu, mlo, 1));
        mlo = fmaxf(mlo, __shfl_xor_sync(0xffffffffu, mlo, 2));
        mhi = fmaxf(mhi, __shfl_xor_sync(0xffffffffu, mhi, 1));
        mhi = fmaxf(mhi, __shfl_xor_sync(0xffffffffu, mhi, 2));
        float mnl = fmaxf(m_l, mlo), mnh = fmaxf(m_h, mhi);
        float scl = ex2f(m_l - mnl), sch = ex2f(m_h - mnh);
        m_l = mnl; m_h = mnh;
        float slo = 0.f, shi = 0.f;
        #pragma unroll
        for (int f = 0; f < 8; f++) {
            float p0 = ex2f(S[f][0] - mnl);
            float p1 = ex2f(S[f][1] - mnl);
            float p2 = ex2f(S[f][2] - mnh);
            float p3 = ex2f(S[f][3] - mnh);
            slo += p0 + p1;
            shi += p2 + p3;
            S[f][0] = p0; S[f][1] = p1; S[f][2] = p2; S[f][3] = p3;
        }
        slo += __shfl_xor_sync(0xffffffffu, slo, 1);
        slo += __shfl_xor_sync(0xffffffffu, slo, 2);
        shi += __shfl_xor_sync(0xffffffffu, shi, 1);
        shi += __shfl_xor_sync(0xffffffffu, shi, 2);
        l_l = l_l * scl + slo;
        l_h = l_h * sch + shi;

        if (!__all_sync(0xffffffffu, (scl == 1.f) && (sch == 1.f))) {
            #pragma unroll
            for (int cf = 0; cf < 16; cf++) {
                O[cf][0] *= scl; O[cf][1] *= scl;
                O[cf][2] *= sch; O[cf][3] *= sch;
            }
        }
        #pragma unroll
        for (int kc = 0; kc < 4; kc++) {
            uint32 a[4];
            a[0] = pack_h2(S[2 * kc][0],     S[2 * kc][1]);
            a[1] = pack_h2(S[2 * kc][2],     S[2 * kc][3]);
            a[2] = pack_h2(S[2 * kc + 1][0], S[2 * kc + 1][1]);
            a[3] = pack_h2(S[2 * kc + 1][2], S[2 * kc + 1][3]);
            const uint2* vr = cV2 + (4 * kc + kk) * 132 + g;
            #pragma unroll
            for (int cf = 0; cf < 16; cf++) {
                uint2 v2 = vr[8 * cf];
                mma_fp16(O[cf], a, v2.x, v2.y);
            }
        }
        if (nt < 15) {
            CP_WAIT0();
            __syncthreads();
        }
    }

    __syncthreads();
    float il2 = 1.0f / l_l, ih3 = 1.0f / l_h;
    float* sO = sm;
    #pragma unroll
    for (int cf = 0; cf < 16; cf++) {
        int col = 8 * cf + 2 * kk;
        *(float2*)&sO[rl * 130 + col] = make_float2(O[cf][0] * il2, O[cf][1] * il2);
        *(float2*)&sO[rh * 130 + col] = make_float2(O[cf][2] * ih3, O[cf][3] * ih3);
    }
    __syncthreads();
    {
        int m = tid & 63;
        int c0 = (tid >> 6) * 64;
        #pragma unroll 4
        for (int k2 = 0; k2 < 64; k2++) {
            int c = c0 + k2;
            size_t a = ((size_t)b * 512 + h * 128 + c) * 1024 + mg + m;
            out[a] = sO[m * 130 + c] + x[a];
        }
    }
}

// ---------------- launch ----------------
extern "C" void kernel_launch(void* const* d_in, const int* in_sizes, int n_in,
                              void* d_out, int out_size)
{
    const float* x     = (const float*)d_in[0];
    const float* Wq    = (const float*)d_in[1];
    const float* bq    = (const float*)d_in[2];
    const float* qg    = (const float*)d_in[3];
    const float* qb    = (const float*)d_in[4];
    const float* qm    = (const float*)d_in[5];
    const float* qv    = (const float*)d_in[6];
    const float* Wk    = (const float*)d_in[7];
    const float* bk    = (const float*)d_in[8];
    const float* kg    = (const float*)d_in[9];
    const float* kb    = (const float*)d_in[10];
    const float* km    = (const float*)d_in[11];
    const float* kv    = (const float*)d_in[12];
    const float* Wv    = (const float*)d_in[13];
    const float* bv    = (const float*)d_in[14];
    const float* vg    = (const float*)d_in[15];
    const float* vb    = (const float*)d_in[16];
    const float* vm    = (const float*)d_in[17];
    const float* vvar  = (const float*)d_in[18];
    const float* rel_h = (const float*)d_in[19];
    const float* rel_w = (const float*)d_in[20];
    float* out = (float*)d_out;

    cudaFuncSetAttribute(attn_kernel, cudaFuncAttributeMaxDynamicSharedMemorySize,
                         ATTN_SMEM_FLOATS * (int)sizeof(float));
    cudaFuncSetAttribute(proj_kernel, cudaFuncAttributeMaxDynamicSharedMemorySize,
                         PROJ_SMEM_BYTES);

    fold_kernel<<<768, 256>>>(Wq, bq, qg, qb, qm, qv,
                              Wk, bk, kg, kb, km, kv,
                              Wv, bv, vg, vb, vm, vvar);
    xsplit_kernel<<<dim3(256, 16), 256>>>(x);
    proj_kernel<<<dim3(8, 6, 16), 256, PROJ_SMEM_BYTES>>>();
    prep_kernel<<<dim3(16, 4, 16), 256>>>();
    posq_kernel<<<dim3(16, 4, 16), 256>>>(rel_h, rel_w);
    attn_kernel<<<dim3(16, 4, 16), 128, ATTN_SMEM_FLOATS * sizeof(float)>>>(x, out);
}

// round 15
// speedup vs baseline: 1.1190x; 1.1190x over previous
#include <cuda_runtime.h>
#include <cuda_bf16.h>
#include <cuda_fp16.h>

typedef unsigned int uint32;

#define EPS 1e-5f
#define TILE_F 9216    // floats per tile image: K-bf16split 4224 + V-fp16 4224 + pad

// ---------------- scratch (device globals; no cudaMalloc allowed) ----------------
__device__ float g_ball[768];               // folded biases
__device__ float g_qk[16 * 256 * 1024];     // [b][o][n]; only q rows (o<128) are written/read now
__device__ __align__(16) uint2 g_Wbs[768 * 256];        // W big/small bf16 pairs [o][kpair]
__device__ __align__(16) uint2 g_Xbs[16 * 256 * 1024];  // X big/small bf16 pairs [b][kpair][n]
__device__ __align__(16) uint32 g_Wh[768 * 256];        // W fp16 pairs [o][kpair]
__device__ __align__(16) uint32 g_Xh[16 * 256 * 1024];  // X fp16 pairs [b][kpair][n]
__device__ __align__(16) float g_tile[16 * 4 * 16 * TILE_F]; // fragment-ready K'/V tiles

// ---------------- mma / pack helpers ----------------
__device__ __forceinline__ void mma_bf16(float* c, const uint32* a, uint32 b0, uint32 b1) {
    asm volatile("mma.sync.aligned.m16n8k16.row.col.f32.bf16.bf16.f32 "
        "{%0,%1,%2,%3}, {%4,%5,%6,%7}, {%8,%9}, {%0,%1,%2,%3};"
        : "+f"(c[0]), "+f"(c[1]), "+f"(c[2]), "+f"(c[3])
        : "r"(a[0]), "r"(a[1]), "r"(a[2]), "r"(a[3]), "r"(b0), "r"(b1));
}
__device__ __forceinline__ void mma_fp16(float* c, const uint32* a, uint32 b0, uint32 b1) {
    asm volatile("mma.sync.aligned.m16n8k16.row.col.f32.f16.f16.f32 "
        "{%0,%1,%2,%3}, {%4,%5,%6,%7}, {%8,%9}, {%0,%1,%2,%3};"
        : "+f"(c[0]), "+f"(c[1]), "+f"(c[2]), "+f"(c[3])
        : "r"(a[0]), "r"(a[1]), "r"(a[2]), "r"(a[3]), "r"(b0), "r"(b1));
}

// split v0,v1 into bf16 big/small packed pairs (element0 in low 16 bits)
__device__ __forceinline__ void split2_bf(float v0, float v1, uint32& bb, uint32& ss) {
    float b0 = __bfloat162float(__float2bfloat16_rn(v0));
    float b1 = __bfloat162float(__float2bfloat16_rn(v1));
    __nv_bfloat162 tb = __floats2bfloat162_rn(b0, b1);
    __nv_bfloat162 ts = __floats2bfloat162_rn(v0 - b0, v1 - b1);
    bb = *reinterpret_cast<uint32*>(&tb);
    ss = *reinterpret_cast<uint32*>(&ts);
}
__device__ __forceinline__ uint32 pack_h2(float v0, float v1) {
    __half2 h = __floats2half2_rn(v0, v1);
    return *reinterpret_cast<uint32*>(&h);
}
__device__ __forceinline__ float ex2f(float x) {
    float r; asm("ex2.approx.ftz.f32 %0, %1;" : "=f"(r) : "f"(x)); return r;
}

// ---------------- cp.async helpers ----------------
__device__ __forceinline__ void cp16(uint32 sdst, const void* gsrc) {
    asm volatile("cp.async.cg.shared.global [%0], [%1], 16;\n" :: "r"(sdst), "l"(gsrc));
}
#define CP_COMMIT() asm volatile("cp.async.commit_group;\n" ::: "memory")
#define CP_WAIT0()  asm volatile("cp.async.wait_group 0;\n" ::: "memory")
#define CP_WAIT1()  asm volatile("cp.async.wait_group 1;\n" ::: "memory")

// 128-thread tile copy for attn
__device__ __forceinline__ void cp_tile(float* smem_dst, const float* gsrc, int tid) {
    uint32 s = (uint32)__cvta_generic_to_shared(smem_dst);
    #pragma unroll
    for (int it = 0; it < 18; it++) {
        int i = tid + it * 128;          // 2304 float4s = 9216 floats
        cp16(s + i * 16, gsrc + i * 4);
    }
}

// ---------------- 1) fold BN into conv weights; write bf16-split + fp16 images ----------------
__global__ void fold_kernel(
    const float* __restrict__ Wq, const float* __restrict__ bq,
    const float* __restrict__ qg, const float* __restrict__ qb,
    const float* __restrict__ qm, const float* __restrict__ qvv,
    const float* __restrict__ Wk, const float* __restrict__ bk,
    const float* __restrict__ kg, const float* __restrict__ kb,
    const float* __restrict__ km, const float* __restrict__ kvv,
    const float* __restrict__ Wv, const float* __restrict__ bv,
    const float* __restrict__ vg, const float* __restrict__ vb,
    const float* __restrict__ vm, const float* __restrict__ vvv)
{
    int o = blockIdx.x;  // 0..767
    const float* src;
    float s, bias;
    if (o < 128) {
        s = qg[o] * rsqrtf(qvv[o] + EPS);
        bias = (bq[o] - qm[o]) * s + qb[o];
        src = Wq + o * 512;
    } else if (o < 256) {
        int oo = o - 128;
        s = kg[oo] * rsqrtf(kvv[oo] + EPS);
        bias = (bk[oo] - km[oo]) * s + kb[oo];
        src = Wk + oo * 512;
    } else {
        int oo = o - 256;
        s = vg[oo] * rsqrtf(vvv[oo] + EPS);
        bias = (bv[oo] - vm[oo]) * s + vb[oo];
        src = Wv + oo * 512;
    }
    int p = threadIdx.x;           // pair 0..255
    float w0 = src[2 * p] * s;
    float w1 = src[2 * p + 1] * s;
    uint32 bb, ss;
    split2_bf(w0, w1, bb, ss);
    g_Wbs[o * 256 + p] = make_uint2(bb, ss);
    g_Wh[o * 256 + p] = pack_h2(w0, w1);
    if (p == 0) g_ball[o] = bias;
}

// ---------------- 2) pre-split X into bf16 big/small + fp16 pair images ----------------
__global__ __launch_bounds__(256) void xsplit_kernel(const float* __restrict__ x) {
    int kp = blockIdx.x, b = blockIdx.y;
    int tid = threadIdx.x;
    const float* r0 = x + ((size_t)b * 512 + 2 * kp) * 1024;
    const float* r1 = r0 + 1024;
    uint2* dst = g_Xbs + ((size_t)b * 256 + kp) * 1024;
    uint32* dsth = g_Xh + ((size_t)b * 256 + kp) * 1024;
    int n4 = tid * 4;
    float4 a = *(const float4*)&r0[n4];
    float4 c = *(const float4*)&r1[n4];
    uint2 o0, o1, o2, o3;
    split2_bf(a.x, c.x, o0.x, o0.y);
    split2_bf(a.y, c.y, o1.x, o1.y);
    split2_bf(a.z, c.z, o2.x, o2.y);
    split2_bf(a.w, c.w, o3.x, o3.y);
    dst[n4] = o0; dst[n4 + 1] = o1; dst[n4 + 2] = o2; dst[n4 + 3] = o3;
    uint4 hv;
    hv.x = pack_h2(a.x, c.x);
    hv.y = pack_h2(a.y, c.y);
    hv.z = pack_h2(a.z, c.z);
    hv.w = pack_h2(a.w, c.w);
    *(uint4*)&dsth[n4] = hv;
}

// ---------------- 3) QKV projection (3-stage cp.async pipeline) ----------------
// QK blocks (rb<2): bf16 3-term compensated. q block (rb=0) -> g_qk + K-image dp8-15.
//                   k block (rb=1) -> K-image dp0-7 only.
// V blocks (rb>=2): fp16 single-term -> fp16 V tile image in g_tile (direct).
#define PBQK_U2 4672
#define PBV_U1 4736
#define PROJ_SMEM_BYTES 112128   // 3 * PBQK_U2 * 8; covers V (3*18944) and epilogue (67584)

__device__ __forceinline__ void cp_projqk(uint2* buf, int b, int row0, int col0, int kt, int tid) {
    uint32 s = (uint32)__cvta_generic_to_shared(buf);
    #pragma unroll
    for (int it = 0; it < 4; it++) {
        int i = tid + it * 256;
        int m = i >> 3, c = i & 7;
        cp16(s + (m * 20 + 2 * c) * 8, g_Wbs + (size_t)(row0 + m) * 256 + kt * 16 + 2 * c);
    }
    #pragma unroll
    for (int it = 0; it < 4; it++) {
        int i = tid + it * 256;
        int kp = i >> 6, c = i & 63;
        cp16(s + (2560 + kp * 132 + 2 * c) * 8,
             g_Xbs + ((size_t)b * 256 + kt * 16 + kp) * 1024 + col0 + 2 * c);
    }
}

__device__ __forceinline__ void cp_projv(uint32* buf, int b, int row0, int col0, int kt, int tid) {
    uint32 s = (uint32)__cvta_generic_to_shared(buf);
    #pragma unroll
    for (int it = 0; it < 2; it++) {
        int i = tid + it * 256;
        int m = i >> 2, c = i & 3;
        cp16(s + (m * 20 + 4 * c) * 4, g_Wh + (size_t)(row0 + m) * 256 + kt * 16 + 4 * c);
    }
    #pragma unroll
    for (int it = 0; it < 2; it++) {
        int i = tid + it * 256;
        int kp = i >> 5, c = i & 31;
        cp16(s + (2560 + kp * 136 + 4 * c) * 4,
             g_Xh + ((size_t)b * 256 + kt * 16 + kp) * 1024 + col0 + 4 * c);
    }
}

__global__ __launch_bounds__(256) void proj_kernel() {
    extern __shared__ float ps[];
    int b = blockIdx.z, row0 = blockIdx.y * 128, col0 = blockIdx.x * 128;
    bool isV = (row0 >= 256);
    int tid = threadIdx.x, w = tid >> 5, lane = tid & 31;
    int g = lane >> 2, kk = lane & 3;
    int wm = w >> 1, wn = w & 1;

    float acc[2][8][4];
    #pragma unroll
    for (int mi = 0; mi < 2; mi++)
        #pragma unroll
        for (int nf = 0; nf < 8; nf++)
            #pragma unroll
            for (int j = 0; j < 4; j++) acc[mi][nf][j] = 0.f;

    if (!isV) {
        // ---------- bf16 3-term path (q/k), 3-stage pipeline ----------
        uint2* sbase = (uint2*)ps;
        cp_projqk(sbase, b, row0, col0, 0, tid);
        CP_COMMIT();
        cp_projqk(sbase + PBQK_U2, b, row0, col0, 1, tid);
        CP_COMMIT();
        int bufidx = 0;
        for (int kt = 0; kt < 16; kt++) {
            if (kt == 15) CP_WAIT0(); else CP_WAIT1();
            __syncthreads();
            if (kt < 14) {
                int nb = bufidx + 2; if (nb >= 3) nb -= 3;
                cp_projqk(sbase + nb * PBQK_U2, b, row0, col0, kt + 2, tid);
                CP_COMMIT();
            }
            uint2* cur = sbase + bufidx * PBQK_U2;
            uint2* sW = cur;
            uint2* sX = cur + 2560;
            #pragma unroll
            for (int kc = 0; kc < 2; kc++) {
                uint32 Ab[2][4], As[2][4];
                #pragma unroll
                for (int mi = 0; mi < 2; mi++) {
                    int r = wm * 32 + mi * 16 + g;
                    uint2 w0 = sW[r * 20 + kk + 8 * kc];
                    uint2 w1 = sW[(r + 8) * 20 + kk + 8 * kc];
                    uint2 w2 = sW[r * 20 + kk + 4 + 8 * kc];
                    uint2 w3 = sW[(r + 8) * 20 + kk + 4 + 8 * kc];
                    Ab[mi][0] = w0.x; Ab[mi][1] = w1.x; Ab[mi][2] = w2.x; Ab[mi][3] = w3.x;
                    As[mi][0] = w0.y; As[mi][1] = w1.y; As[mi][2] = w2.y; As[mi][3] = w3.y;
                }
                #pragma unroll
                for (int nf = 0; nf < 8; nf++) {
                    int nc = wn * 64 + 8 * nf + g;
                    uint2 x0 = sX[(kk + 8 * kc) * 132 + nc];
                    uint2 x1 = sX[(kk + 4 + 8 * kc) * 132 + nc];
                    #pragma unroll
                    for (int mi = 0; mi < 2; mi++) {
                        mma_bf16(acc[mi][nf], Ab[mi], x0.x, x1.x);
                        mma_bf16(acc[mi][nf], As[mi], x0.x, x1.x);
                        mma_bf16(acc[mi][nf], Ab[mi], x0.y, x1.y);
                    }
                }
            }
            if (++bufidx == 3) bufidx = 0;
        }
        bool isQ = (row0 == 0);
        if (isQ) {
            // direct q stores to g_qk (needed by attn Q staging)
            #pragma unroll
            for (int mi = 0; mi < 2; mi++) {
                int o0 = wm * 32 + mi * 16 + g;
                int o1 = o0 + 8;
                float b0v = g_ball[o0], b1v = g_ball[o1];
                #pragma unroll
                for (int nf = 0; nf < 8; nf++) {
                    int n = col0 + wn * 64 + 8 * nf + 2 * kk;
                    *(float2*)&g_qk[((size_t)b * 256 + o0) * 1024 + n] =
                        make_float2(acc[mi][nf][0] + b0v, acc[mi][nf][1] + b0v);
                    *(float2*)&g_qk[((size_t)b * 256 + o1) * 1024 + n] =
                        make_float2(acc[mi][nf][2] + b1v, acc[mi][nf][3] + b1v);
                }
            }
        }
        // stage sOut[n][ol] and write this block's K-image half
        __syncthreads();
        float* sOut = ps;   // 128 n x 132
        #pragma unroll
        for (int mi = 0; mi < 2; mi++) {
            int o0 = row0 + wm * 32 + mi * 16 + g;
            int ol = wm * 32 + mi * 16 + g;
            float b0v = g_ball[o0], b1v = g_ball[o0 + 8];
            #pragma unroll
            for (int nf = 0; nf < 8; nf++) {
                int n = wn * 64 + 8 * nf + 2 * kk;
                sOut[n * 132 + ol] = acc[mi][nf][0] + b0v;
                sOut[(n + 1) * 132 + ol] = acc[mi][nf][1] + b0v;
                sOut[n * 132 + ol + 8] = acc[mi][nf][2] + b1v;
                sOut[(n + 1) * 132 + ol + 8] = acc[mi][nf][3] + b1v;
            }
        }
        __syncthreads();
        int dpbase = isQ ? 8 : 0;    // q rows -> K' rows 32-63 (dp 8-15); k rows -> dp 0-7
        #pragma unroll
        for (int it = 0; it < 16; it++) {
            int idx = tid + it * 256;   // 4096: n 0..63 | dpo 0..7 | h 0..3 | ntl 0..1
            int n = idx & 63, dpo = (idx >> 6) & 7, h = (idx >> 9) & 3, ntl = idx >> 11;
            int dp = dpbase + dpo;
            int kc = dp >> 2, kkp = dp & 3;
            int r0 = 16 * kc + 2 * kkp;          // K' row
            int d = isQ ? (r0 - 32) : r0;        // local row within this block's head slice
            int nl = ntl * 64 + n;
            float2 v01 = *(const float2*)&sOut[nl * 132 + h * 32 + d];
            float2 v89 = *(const float2*)&sOut[nl * 132 + h * 32 + d + 8];
            uint4 o;
            split2_bf(v01.x, v01.y, o.x, o.z);
            split2_bf(v89.x, v89.y, o.y, o.w);
            float* tb = g_tile + ((size_t)((b * 4 + h) * 16) + (col0 >> 6) + ntl) * TILE_F;
            ((uint4*)tb)[dp * 66 + n] = o;
        }
    } else {
        // ---------- fp16 single-term path (v), 3-stage pipeline ----------
        uint32* sbase = (uint32*)ps;
        cp_projv(sbase, b, row0, col0, 0, tid);
        CP_COMMIT();
        cp_projv(sbase + PBV_U1, b, row0, col0, 1, tid);
        CP_COMMIT();
        int bufidx = 0;
        for (int kt = 0; kt < 16; kt++) {
            if (kt == 15) CP_WAIT0(); else CP_WAIT1();
            __syncthreads();
            if (kt < 14) {
                int nb = bufidx + 2; if (nb >= 3) nb -= 3;
                cp_projv(sbase + nb * PBV_U1, b, row0, col0, kt + 2, tid);
                CP_COMMIT();
            }
            uint32* cur = sbase + bufidx * PBV_U1;
            uint32* sW = cur;
            uint32* sX = cur + 2560;
            #pragma unroll
            for (int kc = 0; kc < 2; kc++) {
                uint32 A[2][4];
                #pragma unroll
                for (int mi = 0; mi < 2; mi++) {
                    int r = wm * 32 + mi * 16 + g;
                    A[mi][0] = sW[r * 20 + kk + 8 * kc];
                    A[mi][1] = sW[(r + 8) * 20 + kk + 8 * kc];
                    A[mi][2] = sW[r * 20 + kk + 4 + 8 * kc];
                    A[mi][3] = sW[(r + 8) * 20 + kk + 4 + 8 * kc];
                }
                #pragma unroll
                for (int nf = 0; nf < 8; nf++) {
                    int nc = wn * 64 + 8 * nf + g;
                    uint32 x0 = sX[(kk + 8 * kc) * 136 + nc];
                    uint32 x1 = sX[(kk + 4 + 8 * kc) * 136 + nc];
                    #pragma unroll
                    for (int mi = 0; mi < 2; mi++)
                        mma_fp16(acc[mi][nf], A[mi], x0, x1);
                }
            }
            if (++bufidx == 3) bufidx = 0;
        }
        // epilogue: transpose to sOut[n][c], then write fp16 V tile image directly
        __syncthreads();
        float* sOut = ps;   // 128 n x 132
        #pragma unroll
        for (int mi = 0; mi < 2; mi++) {
            int o0 = row0 + wm * 32 + mi * 16 + g;
            int ol = wm * 32 + mi * 16 + g;
            float b0v = g_ball[o0], b1v = g_ball[o0 + 8];
            #pragma unroll
            for (int nf = 0; nf < 8; nf++) {
                int n = wn * 64 + 8 * nf + 2 * kk;
                sOut[n * 132 + ol] = acc[mi][nf][0] + b0v;
                sOut[(n + 1) * 132 + ol] = acc[mi][nf][1] + b0v;
                sOut[n * 132 + ol + 8] = acc[mi][nf][2] + b1v;
                sOut[(n + 1) * 132 + ol + 8] = acc[mi][nf][3] + b1v;
            }
        }
        __syncthreads();
        int h = (row0 - 256) >> 7;
        float* tb0 = g_tile + ((size_t)((b * 4 + h) * 16) + (col0 >> 6)) * TILE_F + 4224;
        #pragma unroll
        for (int it = 0; it < 16; it++) {
            int idx = tid + it * 256;     // 4096: c 0..127, dp 0..15, ntl 0..1
            int c = idx & 127, dp = (idx >> 7) & 15, ntl = idx >> 11;
            int r0 = 16 * (dp >> 2) + 2 * (dp & 3) + ntl * 64;
            uint2 val = make_uint2(
                pack_h2(sOut[r0 * 132 + c],       sOut[(r0 + 1) * 132 + c]),
                pack_h2(sOut[(r0 + 8) * 132 + c], sOut[(r0 + 9) * 132 + c]));
            ((uint2*)(tb0 + (size_t)ntl * TILE_F))[dp * 132 + c] = val;
        }
    }
}

// ---------------- 4) flash attention: 64-query tiles, 128 threads, 3 CTAs/SM ----------------
#define ATTN_SMEM_FLOATS (2 * TILE_F)   // 18432 floats = 73728 B

__global__ __launch_bounds__(128, 3) void attn_kernel(const float* __restrict__ x,
                                                      const float* __restrict__ rel_h,
                                                      const float* __restrict__ rel_w,
                                                      float* __restrict__ out)
{
    extern __shared__ float sm[];
    int mt = blockIdx.x, h = blockIdx.y, b = blockIdx.z;
    int tid = threadIdx.x, w = tid >> 5, lane = tid & 31;
    int g = lane >> 2, kk = lane & 3;
    int mg = mt * 64;
    int rl = 16 * w + g, rh = rl + 8;
    size_t qkbase = (size_t)b * 256 * 1024;
    const float* tbase = g_tile + (size_t)((b * 4 + h) * 16) * TILE_F;

    cp_tile(sm, tbase, tid);
    CP_COMMIT();

    // stage Q' [64 m][68] (d-major transpose + pos inline)
    float* sQ = sm + TILE_F;
    #pragma unroll
    for (int it = 0; it < 8; it++) {
        int i = tid + it * 128;   // 1024 float4 units: 64 d x 16 m4
        int d = i >> 4, m4 = (i & 15) << 2;
        float4 v;
        if (d < 32) {
            v = *(const float4*)&g_qk[qkbase + (size_t)(h * 32 + d) * 1024 + mg + m4];
        } else {
            int hd = h * 32 + (d - 32);
            int n0 = mg + m4;
            float ww = rel_w[hd * 32 + (n0 >> 5)];
            float4 rh4 = *(const float4*)&rel_h[hd * 32 + (n0 & 31)];
            v = make_float4(rh4.x + ww, rh4.y + ww, rh4.z + ww, rh4.w + ww);
        }
        sQ[(m4 + 0) * 68 + d] = v.x;
        sQ[(m4 + 1) * 68 + d] = v.y;
        sQ[(m4 + 2) * 68 + d] = v.z;
        sQ[(m4 + 3) * 68 + d] = v.w;
    }
    __syncthreads();

    const float LOG2E = 1.4426950408889634f;
    uint32 Qb[4][4], Qs[4][4];
    #pragma unroll
    for (int kc = 0; kc < 4; kc++) {
        int klo = 16 * kc + 2 * kk;
        int khi = klo + 8;
        split2_bf(LOG2E * sQ[rl * 68 + klo], LOG2E * sQ[rl * 68 + klo + 1], Qb[kc][0], Qs[kc][0]);
        split2_bf(LOG2E * sQ[rh * 68 + klo], LOG2E * sQ[rh * 68 + klo + 1], Qb[kc][1], Qs[kc][1]);
        split2_bf(LOG2E * sQ[rl * 68 + khi], LOG2E * sQ[rl * 68 + khi + 1], Qb[kc][2], Qs[kc][2]);
        split2_bf(LOG2E * sQ[rh * 68 + khi], LOG2E * sQ[rh * 68 + khi + 1], Qb[kc][3], Qs[kc][3]);
    }
    float m_l = -1e30f, m_h = -1e30f, l_l = 0.f, l_h = 0.f;
    float O[16][4];
    #pragma unroll
    for (int cf = 0; cf < 16; cf++)
        #pragma unroll
        for (int j = 0; j < 4; j++) O[cf][j] = 0.f;

    CP_WAIT0();
    __syncthreads();

    for (int nt = 0; nt < 16; nt++) {
        float* buf = sm + (nt & 1) * TILE_F;
        if (nt < 15) {
            cp_tile(sm + ((nt + 1) & 1) * TILE_F, tbase + (size_t)(nt + 1) * TILE_F, tid);
            CP_COMMIT();
        }
        const uint4* cK4 = (const uint4*)buf;
        const uint2* cV2 = (const uint2*)(buf + 4224);

        float S[8][4];
        #pragma unroll
        for (int f = 0; f < 8; f++)
            #pragma unroll
            for (int j = 0; j < 4; j++) S[f][j] = 0.f;
        #pragma unroll
        for (int kc = 0; kc < 4; kc++) {
            const uint4* kr = cK4 + (4 * kc + kk) * 66 + g;
            #pragma unroll
            for (int f = 0; f < 8; f++) {
                uint4 kb = kr[8 * f];
                mma_bf16(S[f], Qb[kc], kb.x, kb.y);
                mma_bf16(S[f], Qs[kc], kb.x, kb.y);
                mma_bf16(S[f], Qb[kc], kb.z, kb.w);
            }
        }

        float mlo = -1e30f, mhi = -1e30f;
        #pragma unroll
        for (int f = 0; f < 8; f++) {
            mlo = fmaxf(mlo, fmaxf(S[f][0], S[f][1]));
            mhi = fmaxf(mhi, fmaxf(S[f][2], S[f][3]));
        }
        mlo = fmaxf(mlo, __shfl_xor_sync(0xffffffffu, mlo, 1));
        mlo = fmaxf(mlo, __shfl_xor_sync(0xffffffffu, mlo, 2));
        mhi = fmaxf(mhi, __shfl_xor_sync(0xffffffffu, mhi, 1));
        mhi = fmaxf(mhi, __shfl_xor_sync(0xffffffffu, mhi, 2));
        float mnl = fmaxf(m_l, mlo), mnh = fmaxf(m_h, mhi);
        float scl = ex2f(m_l - mnl), sch = ex2f(m_h - mnh);
        m_l = mnl; m_h = mnh;
        float slo = 0.f, shi = 0.f;
        #pragma unroll
        for (int f = 0; f < 8; f++) {
            float p0 = ex2f(S[f][0] - mnl);
            float p1 = ex2f(S[f][1] - mnl);
            float p2 = ex2f(S[f][2] - mnh);
            float p3 = ex2f(S[f][3] - mnh);
            slo += p0 + p1;
            shi += p2 + p3;
            S[f][0] = p0; S[f][1] = p1; S[f][2] = p2; S[f][3] = p3;
        }
        slo += __shfl_xor_sync(0xffffffffu, slo, 1);
        slo += __shfl_xor_sync(0xffffffffu, slo, 2);
        shi += __shfl_xor_sync(0xffffffffu, shi, 1);
        shi += __shfl_xor_sync(0xffffffffu, shi, 2);
        l_l = l_l * scl + slo;
        l_h = l_h * sch + shi;

        if (!__all_sync(0xffffffffu, (scl == 1.f) && (sch == 1.f))) {
            #pragma unroll
            for (int cf = 0; cf < 16; cf++) {
                O[cf][0] *= scl; O[cf][1] *= scl;
                O[cf][2] *= sch; O[cf][3] *= sch;
            }
        }
        #pragma unroll
        for (int kc = 0; kc < 4; kc++) {
            uint32 a[4];
            a[0] = pack_h2(S[2 * kc][0],     S[2 * kc][1]);
            a[1] = pack_h2(S[2 * kc][2],     S[2 * kc][3]);
            a[2] = pack_h2(S[2 * kc + 1][0], S[2 * kc + 1][1]);
            a[3] = pack_h2(S[2 * kc + 1][2], S[2 * kc + 1][3]);
            const uint2* vr = cV2 + (4 * kc + kk) * 132 + g;
            #pragma unroll
            for (int cf = 0; cf < 16; cf++) {
                uint2 v2 = vr[8 * cf];
                mma_fp16(O[cf], a, v2.x, v2.y);
            }
        }
        if (nt < 15) {
            CP_WAIT0();
            __syncthreads();
        }
    }

    __syncthreads();
    float il = 1.0f / l_l, ih = 1.0f / l_h;
    float* sO = sm;
    #pragma unroll
    for (int cf = 0; cf < 16; cf++) {
        int col = 8 * cf + 2 * kk;
        *(float2*)&sO[rl * 130 + col] = make_float2(O[cf][0] * il, O[cf][1] * il);
        *(float2*)&sO[rh * 130 + col] = make_float2(O[cf][2] * ih, O[cf][3] * ih);
    }
    __syncthreads();
    {
        int m = tid & 63;
        int c0 = (tid >> 6) * 64;
        #pragma unroll 4
        for (int k2 = 0; k2 < 64; k2++) {
            int c = c0 + k2;
            size_t a = ((size_t)b * 512 + h * 128 + c) * 1024 + mg + m;
            out[a] = sO[m * 130 + c] + x[a];
        }
    }
}

// ---------------- launch ----------------
extern "C" void kernel_launch(void* const* d_in, const int* in_sizes, int n_in,
                              void* d_out, int out_size)
{
    const float* x     = (const float*)d_in[0];
    const float* Wq    = (const float*)d_in[1];
    const float* bq    = (const float*)d_in[2];
    const float* qg    = (const float*)d_in[3];
    const float* qb    = (const float*)d_in[4];
    const float* qm    = (const float*)d_in[5];
    const float* qv    = (const float*)d_in[6];
    const float* Wk    = (const float*)d_in[7];
    const float* bk    = (const float*)d_in[8];
    const float* kg    = (const float*)d_in[9];
    const float* kb    = (const float*)d_in[10];
    const float* km    = (const float*)d_in[11];
    const float* kv    = (const float*)d_in[12];
    const float* Wv    = (const float*)d_in[13];
    const float* bv    = (const float*)d_in[14];
    const float* vg    = (const float*)d_in[15];
    const float* vb    = (const float*)d_in[16];
    const float* vm    = (const float*)d_in[17];
    const float* vvar  = (const float*)d_in[18];
    const float* rel_h = (const float*)d_in[19];
    const float* rel_w = (const float*)d_in[20];
    float* out = (float*)d_out;

    cudaFuncSetAttribute(attn_kernel, cudaFuncAttributeMaxDynamicSharedMemorySize,
                         ATTN_SMEM_FLOATS * (int)sizeof(float));
    cudaFuncSetAttribute(proj_kernel, cudaFuncAttributeMaxDynamicSharedMemorySize,
                         PROJ_SMEM_BYTES);

    fold_kernel<<<768, 256>>>(Wq, bq, qg, qb, qm, qv,
                              Wk, bk, kg, kb, km, kv,
                              Wv, bv, vg, vb, vm, vvar);
    xsplit_kernel<<<dim3(256, 16), 256>>>(x);
    proj_kernel<<<dim3(8, 6, 16), 256, PROJ_SMEM_BYTES>>>();
    attn_kernel<<<dim3(16, 4, 16), 128, ATTN_SMEM_FLOATS * sizeof(float)>>>(x, rel_h, rel_w, out);
}

// round 17
// speedup vs baseline: 1.1225x; 1.0031x over previous
#include <cuda_runtime.h>
#include <cuda_bf16.h>
#include <cuda_fp16.h>

typedef unsigned int uint32;

#define EPS 1e-5f
#define TILE_F 9216    // floats per tile image: K-bf16split 4224 + V-fp16 4224 + pad

// ---------------- scratch (device globals; no cudaMalloc allowed) ----------------
__device__ float g_ball[768];               // folded biases
__device__ float g_qk[16 * 256 * 1024];     // [b][o][n]; only q rows (o<128) are written/read now
__device__ __align__(16) uint2 g_Wbs[768 * 256];        // W big/small bf16 pairs [o][kpair]
__device__ __align__(16) uint2 g_Xbs[16 * 256 * 1024];  // X big/small bf16 pairs [b][kpair][n]
__device__ __align__(16) uint32 g_Wh[768 * 256];        // W fp16 pairs [o][kpair]
__device__ __align__(16) uint32 g_Xh[16 * 256 * 1024];  // X fp16 pairs [b][kpair][n]
__device__ __align__(16) float g_tile[16 * 4 * 16 * TILE_F]; // fragment-ready K'/V tiles

// ---------------- mma / pack helpers ----------------
__device__ __forceinline__ void mma_bf16(float* c, const uint32* a, uint32 b0, uint32 b1) {
    asm volatile("mma.sync.aligned.m16n8k16.row.col.f32.bf16.bf16.f32 "
        "{%0,%1,%2,%3}, {%4,%5,%6,%7}, {%8,%9}, {%0,%1,%2,%3};"
        : "+f"(c[0]), "+f"(c[1]), "+f"(c[2]), "+f"(c[3])
        : "r"(a[0]), "r"(a[1]), "r"(a[2]), "r"(a[3]), "r"(b0), "r"(b1));
}
__device__ __forceinline__ void mma_fp16(float* c, const uint32* a, uint32 b0, uint32 b1) {
    asm volatile("mma.sync.aligned.m16n8k16.row.col.f32.f16.f16.f32 "
        "{%0,%1,%2,%3}, {%4,%5,%6,%7}, {%8,%9}, {%0,%1,%2,%3};"
        : "+f"(c[0]), "+f"(c[1]), "+f"(c[2]), "+f"(c[3])
        : "r"(a[0]), "r"(a[1]), "r"(a[2]), "r"(a[3]), "r"(b0), "r"(b1));
}

// split v0,v1 into bf16 big/small packed pairs (element0 in low 16 bits)
__device__ __forceinline__ void split2_bf(float v0, float v1, uint32& bb, uint32& ss) {
    float b0 = __bfloat162float(__float2bfloat16_rn(v0));
    float b1 = __bfloat162float(__float2bfloat16_rn(v1));
    __nv_bfloat162 tb = __floats2bfloat162_rn(b0, b1);
    __nv_bfloat162 ts = __floats2bfloat162_rn(v0 - b0, v1 - b1);
    bb = *reinterpret_cast<uint32*>(&tb);
    ss = *reinterpret_cast<uint32*>(&ts);
}
__device__ __forceinline__ uint32 pack_h2(float v0, float v1) {
    __half2 h = __floats2half2_rn(v0, v1);
    return *reinterpret_cast<uint32*>(&h);
}
__device__ __forceinline__ float ex2f(float x) {
    float r; asm("ex2.approx.ftz.f32 %0, %1;" : "=f"(r) : "f"(x)); return r;
}
__device__ __forceinline__ uint32 h2exp2u(uint32 x) {
    uint32 r; asm("ex2.approx.f16x2 %0, %1;" : "=r"(r) : "r"(x)); return r;
}

// ---------------- cp.async helpers ----------------
__device__ __forceinline__ void cp16(uint32 sdst, const void* gsrc) {
    asm volatile("cp.async.cg.shared.global [%0], [%1], 16;\n" :: "r"(sdst), "l"(gsrc));
}
#define CP_COMMIT() asm volatile("cp.async.commit_group;\n" ::: "memory")
#define CP_WAIT0()  asm volatile("cp.async.wait_group 0;\n" ::: "memory")
#define CP_WAIT1()  asm volatile("cp.async.wait_group 1;\n" ::: "memory")

// 128-thread tile copy for attn
__device__ __forceinline__ void cp_tile(float* smem_dst, const float* gsrc, int tid) {
    uint32 s = (uint32)__cvta_generic_to_shared(smem_dst);
    #pragma unroll
    for (int it = 0; it < 18; it++) {
        int i = tid + it * 128;          // 2304 float4s = 9216 floats
        cp16(s + i * 16, gsrc + i * 4);
    }
}

// ---------------- 1) fold BN into conv weights; write bf16-split + fp16 images ----------------
__global__ void fold_kernel(
    const float* __restrict__ Wq, const float* __restrict__ bq,
    const float* __restrict__ qg, const float* __restrict__ qb,
    const float* __restrict__ qm, const float* __restrict__ qvv,
    const float* __restrict__ Wk, const float* __restrict__ bk,
    const float* __restrict__ kg, const float* __restrict__ kb,
    const float* __restrict__ km, const float* __restrict__ kvv,
    const float* __restrict__ Wv, const float* __restrict__ bv,
    const float* __restrict__ vg, const float* __restrict__ vb,
    const float* __restrict__ vm, const float* __restrict__ vvv)
{
    int o = blockIdx.x;  // 0..767
    const float* src;
    float s, bias;
    if (o < 128) {
        s = qg[o] * rsqrtf(qvv[o] + EPS);
        bias = (bq[o] - qm[o]) * s + qb[o];
        src = Wq + o * 512;
    } else if (o < 256) {
        int oo = o - 128;
        s = kg[oo] * rsqrtf(kvv[oo] + EPS);
        bias = (bk[oo] - km[oo]) * s + kb[oo];
        src = Wk + oo * 512;
    } else {
        int oo = o - 256;
        s = vg[oo] * rsqrtf(vvv[oo] + EPS);
        bias = (bv[oo] - vm[oo]) * s + vb[oo];
        src = Wv + oo * 512;
    }
    int p = threadIdx.x;           // pair 0..255
    float w0 = src[2 * p] * s;
    float w1 = src[2 * p + 1] * s;
    uint32 bb, ss;
    split2_bf(w0, w1, bb, ss);
    g_Wbs[o * 256 + p] = make_uint2(bb, ss);
    g_Wh[o * 256 + p] = pack_h2(w0, w1);
    if (p == 0) g_ball[o] = bias;
}

// ---------------- 2) pre-split X into bf16 big/small + fp16 pair images ----------------
__global__ __launch_bounds__(256) void xsplit_kernel(const float* __restrict__ x) {
    int kp = blockIdx.x, b = blockIdx.y;
    int tid = threadIdx.x;
    const float* r0 = x + ((size_t)b * 512 + 2 * kp) * 1024;
    const float* r1 = r0 + 1024;
    uint2* dst = g_Xbs + ((size_t)b * 256 + kp) * 1024;
    uint32* dsth = g_Xh + ((size_t)b * 256 + kp) * 1024;
    int n4 = tid * 4;
    float4 a = *(const float4*)&r0[n4];
    float4 c = *(const float4*)&r1[n4];
    uint2 o0, o1, o2, o3;
    split2_bf(a.x, c.x, o0.x, o0.y);
    split2_bf(a.y, c.y, o1.x, o1.y);
    split2_bf(a.z, c.z, o2.x, o2.y);
    split2_bf(a.w, c.w, o3.x, o3.y);
    dst[n4] = o0; dst[n4 + 1] = o1; dst[n4 + 2] = o2; dst[n4 + 3] = o3;
    uint4 hv;
    hv.x = pack_h2(a.x, c.x);
    hv.y = pack_h2(a.y, c.y);
    hv.z = pack_h2(a.z, c.z);
    hv.w = pack_h2(a.w, c.w);
    *(uint4*)&dsth[n4] = hv;
}

// ---------------- 3) QKV projection (3-stage cp.async pipeline) ----------------
// QK blocks (rb<2): bf16 3-term compensated. q block (rb=0) -> g_qk + K-image dp8-15.
//                   k block (rb=1) -> K-image dp0-7 only.
// V blocks (rb>=2): fp16 single-term -> fp16 V tile image in g_tile (direct).
#define PBQK_U2 4672
#define PBV_U1 4736
#define PROJ_SMEM_BYTES 112128   // 3 * PBQK_U2 * 8; covers V (3*18944) and epilogue (67584)

__device__ __forceinline__ void cp_projqk(uint2* buf, int b, int row0, int col0, int kt, int tid) {
    uint32 s = (uint32)__cvta_generic_to_shared(buf);
    #pragma unroll
    for (int it = 0; it < 4; it++) {
        int i = tid + it * 256;
        int m = i >> 3, c = i & 7;
        cp16(s + (m * 20 + 2 * c) * 8, g_Wbs + (size_t)(row0 + m) * 256 + kt * 16 + 2 * c);
    }
    #pragma unroll
    for (int it = 0; it < 4; it++) {
        int i = tid + it * 256;
        int kp = i >> 6, c = i & 63;
        cp16(s + (2560 + kp * 132 + 2 * c) * 8,
             g_Xbs + ((size_t)b * 256 + kt * 16 + kp) * 1024 + col0 + 2 * c);
    }
}

__device__ __forceinline__ void cp_projv(uint32* buf, int b, int row0, int col0, int kt, int tid) {
    uint32 s = (uint32)__cvta_generic_to_shared(buf);
    #pragma unroll
    for (int it = 0; it < 2; it++) {
        int i = tid + it * 256;
        int m = i >> 2, c = i & 3;
        cp16(s + (m * 20 + 4 * c) * 4, g_Wh + (size_t)(row0 + m) * 256 + kt * 16 + 4 * c);
    }
    #pragma unroll
    for (int it = 0; it < 2; it++) {
        int i = tid + it * 256;
        int kp = i >> 5, c = i & 31;
        cp16(s + (2560 + kp * 136 + 4 * c) * 4,
             g_Xh + ((size_t)b * 256 + kt * 16 + kp) * 1024 + col0 + 4 * c);
    }
}

__global__ __launch_bounds__(256) void proj_kernel() {
    extern __shared__ float ps[];
    int b = blockIdx.z, row0 = blockIdx.y * 128, col0 = blockIdx.x * 128;
    bool isV = (row0 >= 256);
    int tid = threadIdx.x, w = tid >> 5, lane = tid & 31;
    int g = lane >> 2, kk = lane & 3;
    int wm = w >> 1, wn = w & 1;

    float acc[2][8][4];
    #pragma unroll
    for (int mi = 0; mi < 2; mi++)
        #pragma unroll
        for (int nf = 0; nf < 8; nf++)
            #pragma unroll
            for (int j = 0; j < 4; j++) acc[mi][nf][j] = 0.f;

    if (!isV) {
        // ---------- bf16 3-term path (q/k), 3-stage pipeline ----------
        uint2* sbase = (uint2*)ps;
        cp_projqk(sbase, b, row0, col0, 0, tid);
        CP_COMMIT();
        cp_projqk(sbase + PBQK_U2, b, row0, col0, 1, tid);
        CP_COMMIT();
        int bufidx = 0;
        for (int kt = 0; kt < 16; kt++) {
            if (kt == 15) CP_WAIT0(); else CP_WAIT1();
            __syncthreads();
            if (kt < 14) {
                int nb = bufidx + 2; if (nb >= 3) nb -= 3;
                cp_projqk(sbase + nb * PBQK_U2, b, row0, col0, kt + 2, tid);
                CP_COMMIT();
            }
            uint2* cur = sbase + bufidx * PBQK_U2;
            uint2* sW = cur;
            uint2* sX = cur + 2560;
            #pragma unroll
            for (int kc = 0; kc < 2; kc++) {
                uint32 Ab[2][4], As[2][4];
                #pragma unroll
                for (int mi = 0; mi < 2; mi++) {
                    int r = wm * 32 + mi * 16 + g;
                    uint2 w0 = sW[r * 20 + kk + 8 * kc];
                    uint2 w1 = sW[(r + 8) * 20 + kk + 8 * kc];
                    uint2 w2 = sW[r * 20 + kk + 4 + 8 * kc];
                    uint2 w3 = sW[(r + 8) * 20 + kk + 4 + 8 * kc];
                    Ab[mi][0] = w0.x; Ab[mi][1] = w1.x; Ab[mi][2] = w2.x; Ab[mi][3] = w3.x;
                    As[mi][0] = w0.y; As[mi][1] = w1.y; As[mi][2] = w2.y; As[mi][3] = w3.y;
                }
                #pragma unroll
                for (int nf = 0; nf < 8; nf++) {
                    int nc = wn * 64 + 8 * nf + g;
                    uint2 x0 = sX[(kk + 8 * kc) * 132 + nc];
                    uint2 x1 = sX[(kk + 4 + 8 * kc) * 132 + nc];
                    #pragma unroll
                    for (int mi = 0; mi < 2; mi++) {
                        mma_bf16(acc[mi][nf], Ab[mi], x0.x, x1.x);
                        mma_bf16(acc[mi][nf], As[mi], x0.x, x1.x);
                        mma_bf16(acc[mi][nf], Ab[mi], x0.y, x1.y);
                    }
                }
            }
            if (++bufidx == 3) bufidx = 0;
        }
        bool isQ = (row0 == 0);
        if (isQ) {
            // direct q stores to g_qk (needed by attn Q staging)
            #pragma unroll
            for (int mi = 0; mi < 2; mi++) {
                int o0 = wm * 32 + mi * 16 + g;
                int o1 = o0 + 8;
                float b0v = g_ball[o0], b1v = g_ball[o1];
                #pragma unroll
                for (int nf = 0; nf < 8; nf++) {
                    int n = col0 + wn * 64 + 8 * nf + 2 * kk;
                    *(float2*)&g_qk[((size_t)b * 256 + o0) * 1024 + n] =
                        make_float2(acc[mi][nf][0] + b0v, acc[mi][nf][1] + b0v);
                    *(float2*)&g_qk[((size_t)b * 256 + o1) * 1024 + n] =
                        make_float2(acc[mi][nf][2] + b1v, acc[mi][nf][3] + b1v);
                }
            }
        }
        // stage sOut[n][ol] and write this block's K-image half
        __syncthreads();
        float* sOut = ps;   // 128 n x 132
        #pragma unroll
        for (int mi = 0; mi < 2; mi++) {
            int o0 = row0 + wm * 32 + mi * 16 + g;
            int ol = wm * 32 + mi * 16 + g;
            float b0v = g_ball[o0], b1v = g_ball[o0 + 8];
            #pragma unroll
            for (int nf = 0; nf < 8; nf++) {
                int n = wn * 64 + 8 * nf + 2 * kk;
                sOut[n * 132 + ol] = acc[mi][nf][0] + b0v;
                sOut[(n + 1) * 132 + ol] = acc[mi][nf][1] + b0v;
                sOut[n * 132 + ol + 8] = acc[mi][nf][2] + b1v;
                sOut[(n + 1) * 132 + ol + 8] = acc[mi][nf][3] + b1v;
            }
        }
        __syncthreads();
        int dpbase = isQ ? 8 : 0;    // q rows -> K' rows 32-63 (dp 8-15); k rows -> dp 0-7
        #pragma unroll
        for (int it = 0; it < 16; it++) {
            int idx = tid + it * 256;   // 4096: n 0..63 | dpo 0..7 | h 0..3 | ntl 0..1
            int n = idx & 63, dpo = (idx >> 6) & 7, h = (idx >> 9) & 3, ntl = idx >> 11;
            int dp = dpbase + dpo;
            int kc = dp >> 2, kkp = dp & 3;
            int r0 = 16 * kc + 2 * kkp;          // K' row
            int d = isQ ? (r0 - 32) : r0;        // local row within this block's head slice
            int nl = ntl * 64 + n;
            float2 v01 = *(const float2*)&sOut[nl * 132 + h * 32 + d];
            float2 v89 = *(const float2*)&sOut[nl * 132 + h * 32 + d + 8];
            uint4 o;
            split2_bf(v01.x, v01.y, o.x, o.z);
            split2_bf(v89.x, v89.y, o.y, o.w);
            float* tb = g_tile + ((size_t)((b * 4 + h) * 16) + (col0 >> 6) + ntl) * TILE_F;
            ((uint4*)tb)[dp * 66 + n] = o;
        }
    } else {
        // ---------- fp16 single-term path (v), 3-stage pipeline ----------
        uint32* sbase = (uint32*)ps;
        cp_projv(sbase, b, row0, col0, 0, tid);
        CP_COMMIT();
        cp_projv(sbase + PBV_U1, b, row0, col0, 1, tid);
        CP_COMMIT();
        int bufidx = 0;
        for (int kt = 0; kt < 16; kt++) {
            if (kt == 15) CP_WAIT0(); else CP_WAIT1();
            __syncthreads();
            if (kt < 14) {
                int nb = bufidx + 2; if (nb >= 3) nb -= 3;
                cp_projv(sbase + nb * PBV_U1, b, row0, col0, kt + 2, tid);
                CP_COMMIT();
            }
            uint32* cur = sbase + bufidx * PBV_U1;
            uint32* sW = cur;
            uint32* sX = cur + 2560;
            #pragma unroll
            for (int kc = 0; kc < 2; kc++) {
                uint32 A[2][4];
                #pragma unroll
                for (int mi = 0; mi < 2; mi++) {
                    int r = wm * 32 + mi * 16 + g;
                    A[mi][0] = sW[r * 20 + kk + 8 * kc];
                    A[mi][1] = sW[(r + 8) * 20 + kk + 8 * kc];
                    A[mi][2] = sW[r * 20 + kk + 4 + 8 * kc];
                    A[mi][3] = sW[(r + 8) * 20 + kk + 4 + 8 * kc];
                }
                #pragma unroll
                for (int nf = 0; nf < 8; nf++) {
                    int nc = wn * 64 + 8 * nf + g;
                    uint32 x0 = sX[(kk + 8 * kc) * 136 + nc];
                    uint32 x1 = sX[(kk + 4 + 8 * kc) * 136 + nc];
                    #pragma unroll
                    for (int mi = 0; mi < 2; mi++)
                        mma_fp16(acc[mi][nf], A[mi], x0, x1);
                }
            }
            if (++bufidx == 3) bufidx = 0;
        }
        // epilogue: transpose to sOut[n][c], then write fp16 V tile image directly
        __syncthreads();
        float* sOut = ps;   // 128 n x 132
        #pragma unroll
        for (int mi = 0; mi < 2; mi++) {
            int o0 = row0 + wm * 32 + mi * 16 + g;
            int ol = wm * 32 + mi * 16 + g;
            float b0v = g_ball[o0], b1v = g_ball[o0 + 8];
            #pragma unroll
            for (int nf = 0; nf < 8; nf++) {
                int n = wn * 64 + 8 * nf + 2 * kk;
                sOut[n * 132 + ol] = acc[mi][nf][0] + b0v;
                sOut[(n + 1) * 132 + ol] = acc[mi][nf][1] + b0v;
                sOut[n * 132 + ol + 8] = acc[mi][nf][2] + b1v;
                sOut[(n + 1) * 132 + ol + 8] = acc[mi][nf][3] + b1v;
            }
        }
        __syncthreads();
        int h = (row0 - 256) >> 7;
        float* tb0 = g_tile + ((size_t)((b * 4 + h) * 16) + (col0 >> 6)) * TILE_F + 4224;
        #pragma unroll
        for (int it = 0; it < 16; it++) {
            int idx = tid + it * 256;     // 4096: c 0..127, dp 0..15, ntl 0..1
            int c = idx & 127, dp = (idx >> 7) & 15, ntl = idx >> 11;
            int r0 = 16 * (dp >> 2) + 2 * (dp & 3) + ntl * 64;
            uint2 val = make_uint2(
                pack_h2(sOut[r0 * 132 + c],       sOut[(r0 + 1) * 132 + c]),
                pack_h2(sOut[(r0 + 8) * 132 + c], sOut[(r0 + 9) * 132 + c]));
            ((uint2*)(tb0 + (size_t)ntl * TILE_F))[dp * 132 + c] = val;
        }
    }
}

// ---------------- 4) flash attention: packed-fp16 softmax + ones-column row sums ----------------
#define ATTN_SMEM_FLOATS (2 * TILE_F)   // 18432 floats = 73728 B

__global__ __launch_bounds__(128, 3) void attn_kernel(const float* __restrict__ x,
                                                      const float* __restrict__ rel_h,
                                                      const float* __restrict__ rel_w,
                                                      float* __restrict__ out)
{
    extern __shared__ float sm[];
    int mt = blockIdx.x, h = blockIdx.y, b = blockIdx.z;
    int tid = threadIdx.x, w = tid >> 5, lane = tid & 31;
    int g = lane >> 2, kk = lane & 3;
    int mg = mt * 64;
    int rl = 16 * w + g, rh = rl + 8;
    size_t qkbase = (size_t)b * 256 * 1024;
    const float* tbase = g_tile + (size_t)((b * 4 + h) * 16) * TILE_F;

    cp_tile(sm, tbase, tid);
    CP_COMMIT();

    // stage Q' [64 m][68] (d-major transpose + pos inline)
    float* sQ = sm + TILE_F;
    #pragma unroll
    for (int it = 0; it < 8; it++) {
        int i = tid + it * 128;   // 1024 float4 units: 64 d x 16 m4
        int d = i >> 4, m4 = (i & 15) << 2;
        float4 v;
        if (d < 32) {
            v = *(const float4*)&g_qk[qkbase + (size_t)(h * 32 + d) * 1024 + mg + m4];
        } else {
            int hd = h * 32 + (d - 32);
            int n0 = mg + m4;
            float ww = rel_w[hd * 32 + (n0 >> 5)];
            float4 rh4 = *(const float4*)&rel_h[hd * 32 + (n0 & 31)];
            v = make_float4(rh4.x + ww, rh4.y + ww, rh4.z + ww, rh4.w + ww);
        }
        sQ[(m4 + 0) * 68 + d] = v.x;
        sQ[(m4 + 1) * 68 + d] = v.y;
        sQ[(m4 + 2) * 68 + d] = v.z;
        sQ[(m4 + 3) * 68 + d] = v.w;
    }
    __syncthreads();

    const float LOG2E = 1.4426950408889634f;
    uint32 Qb[4][4], Qs[4][4];
    #pragma unroll
    for (int kc = 0; kc < 4; kc++) {
        int klo = 16 * kc + 2 * kk;
        int khi = klo + 8;
        split2_bf(LOG2E * sQ[rl * 68 + klo], LOG2E * sQ[rl * 68 + klo + 1], Qb[kc][0], Qs[kc][0]);
        split2_bf(LOG2E * sQ[rh * 68 + klo], LOG2E * sQ[rh * 68 + klo + 1], Qb[kc][1], Qs[kc][1]);
        split2_bf(LOG2E * sQ[rl * 68 + khi], LOG2E * sQ[rl * 68 + khi + 1], Qb[kc][2], Qs[kc][2]);
        split2_bf(LOG2E * sQ[rh * 68 + khi], LOG2E * sQ[rh * 68 + khi + 1], Qb[kc][3], Qs[kc][3]);
    }
    float m_l = -1e30f, m_h = -1e30f;
    float O[16][4];
    #pragma unroll
    for (int cf = 0; cf < 16; cf++)
        #pragma unroll
        for (int j = 0; j < 4; j++) O[cf][j] = 0.f;
    float O1[4] = {0.f, 0.f, 0.f, 0.f};    // ones-column accumulator (row sums)
    uint32 ones = (g == 0) ? 0x3C003C00u : 0u;   // half2(1,1) in V-col 0

    CP_WAIT0();
    __syncthreads();

    for (int nt = 0; nt < 16; nt++) {
        float* buf = sm + (nt & 1) * TILE_F;
        if (nt < 15) {
            cp_tile(sm + ((nt + 1) & 1) * TILE_F, tbase + (size_t)(nt + 1) * TILE_F, tid);
            CP_COMMIT();
        }
        const uint4* cK4 = (const uint4*)buf;
        const uint2* cV2 = (const uint2*)(buf + 4224);

        float S[8][4];
        #pragma unroll
        for (int f = 0; f < 8; f++)
            #pragma unroll
            for (int j = 0; j < 4; j++) S[f][j] = 0.f;
        #pragma unroll
        for (int kc = 0; kc < 4; kc++) {
            const uint4* kr = cK4 + (4 * kc + kk) * 66 + g;
            #pragma unroll
            for (int f = 0; f < 8; f++) {
                uint4 kb = kr[8 * f];
                mma_bf16(S[f], Qb[kc], kb.x, kb.y);
                mma_bf16(S[f], Qs[kc], kb.x, kb.y);
                mma_bf16(S[f], Qb[kc], kb.z, kb.w);
            }
        }

        float mlo = -1e30f, mhi = -1e30f;
        #pragma unroll
        for (int f = 0; f < 8; f++) {
            mlo = fmaxf(mlo, fmaxf(S[f][0], S[f][1]));
            mhi = fmaxf(mhi, fmaxf(S[f][2], S[f][3]));
        }
        mlo = fmaxf(mlo, __shfl_xor_sync(0xffffffffu, mlo, 1));
        mlo = fmaxf(mlo, __shfl_xor_sync(0xffffffffu, mlo, 2));
        mhi = fmaxf(mhi, __shfl_xor_sync(0xffffffffu, mhi, 1));
        mhi = fmaxf(mhi, __shfl_xor_sync(0xffffffffu, mhi, 2));
        float mnl = fmaxf(m_l, mlo), mnh = fmaxf(m_h, mhi);
        float scl = ex2f(m_l - mnl), sch = ex2f(m_h - mnh);
        m_l = mnl; m_h = mnh;

        // packed fp16 exp: P halves are directly the PV A-fragments
        uint32 P01[8], P23[8];
        #pragma unroll
        for (int f = 0; f < 8; f++) {
            P01[f] = h2exp2u(pack_h2(S[f][0] - mnl, S[f][1] - mnl));
            P23[f] = h2exp2u(pack_h2(S[f][2] - mnh, S[f][3] - mnh));
        }

        if (!__all_sync(0xffffffffu, (scl == 1.f) && (sch == 1.f))) {
            #pragma unroll
            for (int cf = 0; cf < 16; cf++) {
                O[cf][0] *= scl; O[cf][1] *= scl;
                O[cf][2] *= sch; O[cf][3] *= sch;
            }
            O1[0] *= scl; O1[1] *= scl; O1[2] *= sch; O1[3] *= sch;
        }
        #pragma unroll
        for (int kc = 0; kc < 4; kc++) {
            uint32 a[4];
            a[0] = P01[2 * kc];
            a[1] = P23[2 * kc];
            a[2] = P01[2 * kc + 1];
            a[3] = P23[2 * kc + 1];
            const uint2* vr = cV2 + (4 * kc + kk) * 132 + g;
            #pragma unroll
            for (int cf = 0; cf < 16; cf++) {
                uint2 v2 = vr[8 * cf];
                mma_fp16(O[cf], a, v2.x, v2.y);
            }
            mma_fp16(O1, a, ones, ones);   // row sums
        }
        if (nt < 15) {
            CP_WAIT0();
            __syncthreads();
        }
    }

    // row sums live in col 0 (kk==0 lanes); broadcast within each quad
    float l_l = __shfl_sync(0xffffffffu, O1[0], lane & ~3);
    float l_h = __shfl_sync(0xffffffffu, O1[2], lane & ~3);

    __syncthreads();
    float il = 1.0f / l_l, ih = 1.0f / l_h;
    float* sO = sm;
    #pragma unroll
    for (int cf = 0; cf < 16; cf++) {
        int col = 8 * cf + 2 * kk;
        *(float2*)&sO[rl * 130 + col] = make_float2(O[cf][0] * il, O[cf][1] * il);
        *(float2*)&sO[rh * 130 + col] = make_float2(O[cf][2] * ih, O[cf][3] * ih);
    }
    __syncthreads();
    {
        int m = tid & 63;
        int c0 = (tid >> 6) * 64;
        #pragma unroll 4
        for (int k2 = 0; k2 < 64; k2++) {
            int c = c0 + k2;
            size_t a = ((size_t)b * 512 + h * 128 + c) * 1024 + mg + m;
            out[a] = sO[m * 130 + c] + x[a];
        }
    }
}

// ---------------- launch ----------------
extern "C" void kernel_launch(void* const* d_in, const int* in_sizes, int n_in,
                              void* d_out, int out_size)
{
    const float* x     = (const float*)d_in[0];
    const float* Wq    = (const float*)d_in[1];
    const float* bq    = (const float*)d_in[2];
    const float* qg    = (const float*)d_in[3];
    const float* qb    = (const float*)d_in[4];
    const float* qm    = (const float*)d_in[5];
    const float* qv    = (const float*)d_in[6];
    const float* Wk    = (const float*)d_in[7];
    const float* bk    = (const float*)d_in[8];
    const float* kg    = (const float*)d_in[9];
    const float* kb    = (const float*)d_in[10];
    const float* km    = (const float*)d_in[11];
    const float* kv    = (const float*)d_in[12];
    const float* Wv    = (const float*)d_in[13];
    const float* bv    = (const float*)d_in[14];
    const float* vg    = (const float*)d_in[15];
    const float* vb    = (const float*)d_in[16];
    const float* vm    = (const float*)d_in[17];
    const float* vvar  = (const float*)d_in[18];
    const float* rel_h = (const float*)d_in[19];
    const float* rel_w = (const float*)d_in[20];
    float* out = (float*)d_out;

    cudaFuncSetAttribute(attn_kernel, cudaFuncAttributeMaxDynamicSharedMemorySize,
                         ATTN_SMEM_FLOATS * (int)sizeof(float));
    cudaFuncSetAttribute(proj_kernel, cudaFuncAttributeMaxDynamicSharedMemorySize,
                         PROJ_SMEM_BYTES);

    fold_kernel<<<768, 256>>>(Wq, bq, qg, qb, qm, qv,
                              Wk, bk, kg, kb, km, kv,
                              Wv, bv, vg, vb, vm, vvar);
    xsplit_kernel<<<dim3(256, 16), 256>>>(x);
    proj_kernel<<<dim3(8, 6, 16), 256, PROJ_SMEM_BYTES>>>();
    attn_kernel<<<dim3(16, 4, 16), 128, ATTN_SMEM_FLOATS * sizeof(float)>>>(x, rel_h, rel_w, out);
}